// round 7
// baseline (speedup 1.0000x reference)
#include <cuda_runtime.h>

// SegmenterTensorFlow: windowed framing + overlap-add reconstruction.
// B=8, N=4194304, seg=1024, hop=512 -> NSEG=8191, out_len=N.
//
// d_out layout: X [B, NSEG, SEG] followed by x_rec [B, N].
//
// hop = seg/2 => sample n (s0 = n>>9, m = n&511) contributes to:
//   X[b, s0,   m    ]  (valid while s0 <  NSEG)
//   X[b, s0-1, m+512]  (valid while s0 >= 1)
// x_rec[b,n] = x[b,n] * (v0*aw[m]*sw[m] + v1*aw[m+512]*sw[m+512]).
//
// R7: phase-resident body (register-resident windows, minimal stream loop)
// with R1's launch shape restored: flat 1D grid, 256-thread blocks.
// Each block covers 2 segments per iteration (sub = tid>>7), 8 segments
// total -> 8192 blocks. DRAM-bound floor ~78us kernel; this round trims
// the launch/tail overhead that cost R4/R6 ~2.7us of bench time vs R1.

#define BB    8
#define NN    4194304
#define SEG   1024
#define HOP   512
#define NSEG  8191
#define NSVAL 8192      // s0 takes values 0..8191
#define SPB   8         // segments per block
#define ITERS (SPB/2)   // 2 segments per iteration (256 threads)

__device__ __forceinline__ float4 mul4(float4 a, float4 b) {
    float4 r; r.x = a.x*b.x; r.y = a.y*b.y; r.z = a.z*b.z; r.w = a.w*b.w;
    return r;
}

__global__ __launch_bounds__(256)
void seg_phase_kernel(const float* __restrict__ x,
                      const float* __restrict__ aw,
                      const float* __restrict__ sw,
                      float* __restrict__ Xout,
                      float* __restrict__ rec)
{
    const int tid  = threadIdx.x;            // 0..255
    const int sub  = tid >> 7;               // 0 or 1: which segment of the pair
    const int m    = (tid & 127) << 2;       // float4 phase slot, 0..508

    const int bid  = blockIdx.x;             // 0..8191
    const int b    = bid >> 10;              // 0..7   (1024 blocks per batch)
    const int s_lo = (bid & 1023) * SPB + sub;  // first segment this thread touches

    // Windows: loaded once, register-resident for the whole loop.
    float4 awl = *reinterpret_cast<const float4*>(aw + m);
    float4 awh = *reinterpret_cast<const float4*>(aw + m + HOP);
    float4 swl = *reinterpret_cast<const float4*>(sw + m);
    float4 swh = *reinterpret_cast<const float4*>(sw + m + HOP);
    float4 cwl = mul4(awl, swl);             // rec weight, lo half
    float4 cwh = mul4(awh, swh);             // rec weight, hi half

    const size_t nbase = ((size_t)b << 22) + (size_t)s_lo * HOP + m;
    const float* xp   = x   + nbase;
    float*       recp = rec + nbase;
    float*       X0   = Xout + ((size_t)b * NSEG + s_lo) * SEG + m; // [b,s,m]
    float*       X1   = X0 - HOP;                                   // [b,s-1,m+512]

    #pragma unroll
    for (int k = 0; k < ITERS; ++k) {
        const int  s  = s_lo + 2 * k;
        const bool v0 = (s < NSEG);
        const bool v1 = (s >= 1);

        float4 xv = __ldcs(reinterpret_cast<const float4*>(xp));

        if (v0) __stcs(reinterpret_cast<float4*>(X0), mul4(xv, awl));
        if (v1) __stcs(reinterpret_cast<float4*>(X1), mul4(xv, awh));

        const float w0 = v0 ? 1.0f : 0.0f;
        const float w1 = v1 ? 1.0f : 0.0f;
        float4 r;
        r.x = xv.x * (w0 * cwl.x + w1 * cwh.x);
        r.y = xv.y * (w0 * cwl.y + w1 * cwh.y);
        r.z = xv.z * (w0 * cwl.z + w1 * cwh.z);
        r.w = xv.w * (w0 * cwl.w + w1 * cwh.w);
        __stcs(reinterpret_cast<float4*>(recp), r);

        xp   += 2 * HOP;                     // advance 2 segments
        recp += 2 * HOP;
        X0   += 2 * SEG;
        X1   += 2 * SEG;
    }
}

extern "C" void kernel_launch(void* const* d_in, const int* in_sizes, int n_in,
                              void* d_out, int out_size)
{
    const float* x  = (const float*)d_in[0];
    const float* aw = (const float*)d_in[1];
    const float* sw = (const float*)d_in[2];

    float* Xout = (float*)d_out;
    float* rec  = Xout + (size_t)BB * NSEG * SEG;

    const int blocks = (NSVAL / SPB) * BB;   // 1024 * 8 = 8192
    seg_phase_kernel<<<blocks, 256>>>(x, aw, sw, Xout, rec);
}

// round 8
// speedup vs baseline: 1.0340x; 1.0340x over previous
#include <cuda_runtime.h>

// SegmenterTensorFlow: windowed framing + overlap-add reconstruction.
// B=8, N=4194304, seg=1024, hop=512 -> NSEG=8191, out_len=N.
//
// d_out layout: X [B, NSEG, SEG] followed by x_rec [B, N].
//
// hop = seg/2 => each sample n (s0=n>>9, m=n&511) lies in exactly two segments:
//   X[b, s0,   m    ]  (invalid when s0 == NSEG)
//   X[b, s0-1, m+512]  (invalid when s0 == 0)
// x_rec[b,n] = x[b,n] * (v0*aw[m]*sw[m] + v1*aw[m+512]*sw[m+512]).
//
// R8: exact R1 body (best measured: 78.24us kernel, DRAM 77%, 37 regs) with
// block size 512 instead of 256 — the only untested knob on this structure.
// All other levers (cache policy, MLP, phase-resident windows, launch shape)
// were proven neutral-or-worse in R2-R7; the kernel is DRAM-ceiling-bound
// at ~6.1 TB/s for this 1:3 read:write mix.

#define BB   8
#define NN   4194304
#define SEG  1024
#define HOP  512
#define NSEG 8191

__global__ __launch_bounds__(512)
void seg_olap_kernel(const float* __restrict__ x,
                     const float* __restrict__ aw,
                     const float* __restrict__ sw,
                     float* __restrict__ Xout,
                     float* __restrict__ rec)
{
    long long t = (long long)blockIdx.x * blockDim.x + threadIdx.x;
    long long i = t << 2;                       // element index into [B*N]
    if (i >= (long long)BB * NN) return;

    int b = (int)(i >> 22);                     // N = 2^22
    int n = (int)(i & (NN - 1));
    int m = n & (HOP - 1);                      // uniform mod-512 phase (vec-aligned)
    int s0 = n >> 9;

    const bool v0 = (s0 < NSEG);                // segment s0, offset m
    const bool v1 = (s0 >= 1);                  // segment s0-1, offset m+512

    float4 xv  = *reinterpret_cast<const float4*>(x + i);
    float4 awl = *reinterpret_cast<const float4*>(aw + m);
    float4 awh = *reinterpret_cast<const float4*>(aw + m + HOP);
    float4 swl = *reinterpret_cast<const float4*>(sw + m);
    float4 swh = *reinterpret_cast<const float4*>(sw + m + HOP);

    // X writes (coalesced: consecutive n -> consecutive j within a segment row)
    if (v0) {
        float4 lo;
        lo.x = xv.x * awl.x; lo.y = xv.y * awl.y;
        lo.z = xv.z * awl.z; lo.w = xv.w * awl.w;
        size_t off = ((size_t)b * NSEG + s0) * SEG + m;
        *reinterpret_cast<float4*>(Xout + off) = lo;
    }
    if (v1) {
        float4 hi;
        hi.x = xv.x * awh.x; hi.y = xv.y * awh.y;
        hi.z = xv.z * awh.z; hi.w = xv.w * awh.w;
        size_t off = ((size_t)b * NSEG + (s0 - 1)) * SEG + (m + HOP);
        *reinterpret_cast<float4*>(Xout + off) = hi;
    }

    // overlap-add collapses to pointwise weight
    float w0 = v0 ? 1.0f : 0.0f;
    float w1 = v1 ? 1.0f : 0.0f;
    float4 r;
    r.x = xv.x * (w0 * awl.x * swl.x + w1 * awh.x * swh.x);
    r.y = xv.y * (w0 * awl.y * swl.y + w1 * awh.y * swh.y);
    r.z = xv.z * (w0 * awl.z * swl.z + w1 * awh.z * swh.z);
    r.w = xv.w * (w0 * awl.w * swl.w + w1 * awh.w * swh.w);
    *reinterpret_cast<float4*>(rec + i) = r;
}

extern "C" void kernel_launch(void* const* d_in, const int* in_sizes, int n_in,
                              void* d_out, int out_size)
{
    const float* x  = (const float*)d_in[0];
    const float* aw = (const float*)d_in[1];
    const float* sw = (const float*)d_in[2];

    float* Xout = (float*)d_out;
    float* rec  = Xout + (size_t)BB * NSEG * SEG;

    const long long total_vec4 = ((long long)BB * NN) / 4;   // 8,388,608
    const int threads = 512;
    const int blocks = (int)((total_vec4 + threads - 1) / threads); // 16384

    seg_olap_kernel<<<blocks, threads>>>(x, aw, sw, Xout, rec);
}

// round 9
// speedup vs baseline: 1.0392x; 1.0051x over previous
#include <cuda_runtime.h>

// SegmenterTensorFlow: windowed framing + overlap-add reconstruction.
// B=8, N=4194304, seg=1024, hop=512 -> NSEG=8191, out_len=N.
//
// d_out layout: X [B, NSEG, SEG] followed by x_rec [B, N].
//
// hop = seg/2 => each sample n (s0=n>>9, m=n&511) lies in exactly two segments:
//   X[b, s0,   m    ]  (invalid when s0 == NSEG)
//   X[b, s0-1, m+512]  (invalid when s0 == 0)
// x_rec[b,n] = x[b,n] * (v0*aw[m]*sw[m] + v1*aw[m+512]*sw[m+512]).
//
// R9 (final form): R8 structure (flat 1D, 512-thread blocks, one float4 per
// thread) with all index arithmetic in 32-bit (element index < 2^25, all
// intra-array byte offsets < 2^31). Converged DRAM-ceiling kernel: 8 rounds
// showed 6.0-6.1 TB/s (75-77% DRAM) invariant to cache policy, MLP,
// occupancy, instruction mix, and launch shape; traffic floor = 536.8 MB.

#define BB   8
#define NN   4194304u
#define SEG  1024u
#define HOP  512u
#define NSEG 8191u

__global__ __launch_bounds__(512)
void seg_olap_kernel(const float* __restrict__ x,
                     const float* __restrict__ aw,
                     const float* __restrict__ sw,
                     float* __restrict__ Xout,
                     float* __restrict__ rec)
{
    unsigned t = blockIdx.x * blockDim.x + threadIdx.x;   // < 2^23
    unsigned i = t << 2;                                  // element index, < 2^25

    unsigned b  = i >> 22;                                // N = 2^22
    unsigned n  = i & (NN - 1u);
    unsigned m  = n & (HOP - 1u);                         // mod-512 phase (vec-aligned)
    unsigned s0 = n >> 9;

    const bool v0 = (s0 < NSEG);                          // segment s0, offset m
    const bool v1 = (s0 >= 1u);                           // segment s0-1, offset m+512

    float4 xv  = *reinterpret_cast<const float4*>(x + i);
    float4 awl = *reinterpret_cast<const float4*>(aw + m);
    float4 awh = *reinterpret_cast<const float4*>(aw + m + HOP);
    float4 swl = *reinterpret_cast<const float4*>(sw + m);
    float4 swh = *reinterpret_cast<const float4*>(sw + m + HOP);

    // X writes (coalesced: consecutive n -> consecutive j within a segment row)
    if (v0) {
        float4 lo;
        lo.x = xv.x * awl.x; lo.y = xv.y * awl.y;
        lo.z = xv.z * awl.z; lo.w = xv.w * awl.w;
        unsigned off = (b * NSEG + s0) * SEG + m;         // < 2^26
        *reinterpret_cast<float4*>(Xout + off) = lo;
    }
    if (v1) {
        float4 hi;
        hi.x = xv.x * awh.x; hi.y = xv.y * awh.y;
        hi.z = xv.z * awh.z; hi.w = xv.w * awh.w;
        unsigned off = (b * NSEG + (s0 - 1u)) * SEG + (m + HOP);
        *reinterpret_cast<float4*>(Xout + off) = hi;
    }

    // overlap-add collapses to pointwise weight
    float w0 = v0 ? 1.0f : 0.0f;
    float w1 = v1 ? 1.0f : 0.0f;
    float4 r;
    r.x = xv.x * (w0 * awl.x * swl.x + w1 * awh.x * swh.x);
    r.y = xv.y * (w0 * awl.y * swl.y + w1 * awh.y * swh.y);
    r.z = xv.z * (w0 * awl.z * swl.z + w1 * awh.z * swh.z);
    r.w = xv.w * (w0 * awl.w * swl.w + w1 * awh.w * swh.w);
    *reinterpret_cast<float4*>(rec + i) = r;
}

extern "C" void kernel_launch(void* const* d_in, const int* in_sizes, int n_in,
                              void* d_out, int out_size)
{
    const float* x  = (const float*)d_in[0];
    const float* aw = (const float*)d_in[1];
    const float* sw = (const float*)d_in[2];

    float* Xout = (float*)d_out;
    float* rec  = Xout + (size_t)BB * NSEG * SEG;

    const unsigned total_vec4 = (BB * NN) / 4u;           // 8,388,608 (exact multiple)
    const unsigned threads = 512;
    const unsigned blocks = total_vec4 / threads;         // 16384, no remainder

    seg_olap_kernel<<<blocks, threads>>>(x, aw, sw, Xout, rec);
}